// round 2
// baseline (speedup 1.0000x reference)
#include <cuda_runtime.h>
#include <cstdint>
#include <cstddef>

// Problem constants
#define T_SEQ 2048
#define DM    1024
#define C3    3072
#define NH    16
#define HD    64

// Scratch (device globals: allocation-free per harness rules)
__device__ float g_qkv[(size_t)4096 * 3072];  // [B*T, 3C]  50.3 MB
__device__ float g_att[(size_t)4096 * 1024];  // [B*T, C]   16.8 MB

// ---------------------------------------------------------------------------
// Tiled fp32 GEMM + bias: C[M,N] = A[M,K] @ B[K,N] + bias[N]
// 128x128 block tile, K-step 8, 256 threads, 8x8 micro-tile per thread.
// ---------------------------------------------------------------------------
__global__ __launch_bounds__(256) void gemm_bias_kernel(
    const float* __restrict__ A, const float* __restrict__ B,
    const float* __restrict__ bias, float* __restrict__ C,
    int M, int N, int K)
{
    __shared__ float As[8][132];   // k-major (transposed A tile), padded
    __shared__ float Bs[8][132];

    const int tid = threadIdx.x;
    const int tx  = tid & 15;
    const int ty  = tid >> 4;
    const int m0  = blockIdx.y << 7;
    const int n0  = blockIdx.x << 7;

    const int arow = tid >> 1;          // 0..127
    const int acol = (tid & 1) << 2;    // 0 or 4
    const int brow = tid >> 5;          // 0..7
    const int bcol = (tid & 31) << 2;   // 0..124

    const float* Ap = A + (size_t)(m0 + arow) * K + acol;
    const float* Bp = B + (size_t)brow * N + n0 + bcol;

    float acc[8][8];
#pragma unroll
    for (int i = 0; i < 8; i++)
#pragma unroll
        for (int j = 0; j < 8; j++) acc[i][j] = 0.f;

    for (int k0 = 0; k0 < K; k0 += 8) {
        float4 av = *(const float4*)(Ap + k0);
        float4 bv = *(const float4*)(Bp + (size_t)k0 * N);
        __syncthreads();
        As[acol + 0][arow] = av.x;
        As[acol + 1][arow] = av.y;
        As[acol + 2][arow] = av.z;
        As[acol + 3][arow] = av.w;
        *(float4*)&Bs[brow][bcol] = bv;
        __syncthreads();

#pragma unroll
        for (int kk = 0; kk < 8; kk++) {
            float a[8], b[8];
            float4 t;
            t = *(const float4*)&As[kk][ty << 2];        a[0]=t.x; a[1]=t.y; a[2]=t.z; a[3]=t.w;
            t = *(const float4*)&As[kk][64 + (ty << 2)]; a[4]=t.x; a[5]=t.y; a[6]=t.z; a[7]=t.w;
            t = *(const float4*)&Bs[kk][tx << 2];        b[0]=t.x; b[1]=t.y; b[2]=t.z; b[3]=t.w;
            t = *(const float4*)&Bs[kk][64 + (tx << 2)]; b[4]=t.x; b[5]=t.y; b[6]=t.z; b[7]=t.w;
#pragma unroll
            for (int i = 0; i < 8; i++)
#pragma unroll
                for (int j = 0; j < 8; j++)
                    acc[i][j] = fmaf(a[i], b[j], acc[i][j]);
        }
    }

#pragma unroll
    for (int ib = 0; ib < 2; ib++)
#pragma unroll
        for (int i = 0; i < 4; i++) {
            int r = m0 + ib * 64 + (ty << 2) + i;
#pragma unroll
            for (int jb = 0; jb < 2; jb++) {
                int c = n0 + jb * 64 + (tx << 2);
                float4 o;
                o.x = acc[ib * 4 + i][jb * 4 + 0] + bias[c + 0];
                o.y = acc[ib * 4 + i][jb * 4 + 1] + bias[c + 1];
                o.z = acc[ib * 4 + i][jb * 4 + 2] + bias[c + 2];
                o.w = acc[ib * 4 + i][jb * 4 + 3] + bias[c + 3];
                *(float4*)(C + (size_t)r * N + c) = o;
            }
        }
}

// ---------------------------------------------------------------------------
// Flash attention (fp32, causal). One block = 64 queries of one (b,h).
// qkv layout: [B*T, 3*C], Q at col h*64, K at 1024+h*64, V at 2048+h*64.
// Output written directly in [B, T, H*D] layout (proj-GEMM ready).
// ---------------------------------------------------------------------------
__global__ __launch_bounds__(256) void attn_kernel(
    const float* __restrict__ qkv, float* __restrict__ outa)
{
    extern __shared__ float sm[];
    float (*Qt)[68] = (float(*)[68])(sm);          // Qt[d][m]  (d-major)
    float (*Kt)[68] = (float(*)[68])(sm + 4352);   // Kt[d][s]
    float (*Vs)[68] = (float(*)[68])(sm + 8704);   // Vs[s][d]
    float (*Ps)[68] = (float(*)[68])(sm + 13056);  // Ps[m][s]

    const int bh = blockIdx.y;
    const int b  = bh >> 4;
    const int h  = bh & 15;
    const int m0 = blockIdx.x << 6;
    const int tid = threadIdx.x;
    const int tx  = tid & 15;
    const int ty  = tid >> 4;

    // Load Q tile (transposed into shared)
    const float* qb = qkv + ((size_t)(b * T_SEQ + m0)) * C3 + h * HD;
    for (int i = tid; i < 1024; i += 256) {
        int r = i >> 4, d4 = (i & 15) << 2;
        float4 v = *(const float4*)(qb + (size_t)r * C3 + d4);
        Qt[d4 + 0][r] = v.x; Qt[d4 + 1][r] = v.y;
        Qt[d4 + 2][r] = v.z; Qt[d4 + 3][r] = v.w;
    }

    float mr[4], lr[4], acc[4][4];
#pragma unroll
    for (int i = 0; i < 4; i++) {
        mr[i] = -1e30f; lr[i] = 0.f;
#pragma unroll
        for (int j = 0; j < 4; j++) acc[i][j] = 0.f;
    }

    const int nkb = (m0 >> 6) + 1;   // causal: only key blocks with n0 <= m0
    for (int kb = 0; kb < nkb; kb++) {
        const int n0 = kb << 6;
        const float* kp = qkv + ((size_t)(b * T_SEQ + n0)) * C3 + DM + h * HD;
        const float* vp = kp + DM;

        __syncthreads();   // protect Kt/Vs from previous iteration readers
        for (int i = tid; i < 1024; i += 256) {
            int r = i >> 4, d4 = (i & 15) << 2;
            float4 kv = *(const float4*)(kp + (size_t)r * C3 + d4);
            Kt[d4 + 0][r] = kv.x; Kt[d4 + 1][r] = kv.y;
            Kt[d4 + 2][r] = kv.z; Kt[d4 + 3][r] = kv.w;
            *(float4*)&Vs[r][d4] = *(const float4*)(vp + (size_t)r * C3 + d4);
        }
        __syncthreads();

        // S = Q @ K^T (4x4 per thread)
        float s[4][4];
#pragma unroll
        for (int i = 0; i < 4; i++)
#pragma unroll
            for (int j = 0; j < 4; j++) s[i][j] = 0.f;

#pragma unroll 8
        for (int d = 0; d < 64; d++) {
            float4 qa = *(const float4*)&Qt[d][ty << 2];
            float4 ka = *(const float4*)&Kt[d][tx << 2];
            float a[4]  = {qa.x, qa.y, qa.z, qa.w};
            float bb[4] = {ka.x, ka.y, ka.z, ka.w};
#pragma unroll
            for (int i = 0; i < 4; i++)
#pragma unroll
                for (int j = 0; j < 4; j++)
                    s[i][j] = fmaf(a[i], bb[j], s[i][j]);
        }

        // scale + causal mask (only the diagonal block needs masking)
        const bool diag = (n0 == m0);
#pragma unroll
        for (int i = 0; i < 4; i++) {
            int row = (ty << 2) + i;
#pragma unroll
            for (int j = 0; j < 4; j++) {
                int col = (tx << 2) + j;
                float sv = s[i][j] * 0.125f;
                if (diag && col > row) sv = -1e30f;
                s[i][j] = sv;
            }
        }

        // online softmax, rows reduced over the 16 tx-lanes (width-16 shfl)
#pragma unroll
        for (int i = 0; i < 4; i++) {
            float mx = fmaxf(fmaxf(s[i][0], s[i][1]), fmaxf(s[i][2], s[i][3]));
#pragma unroll
            for (int off = 8; off > 0; off >>= 1)
                mx = fmaxf(mx, __shfl_xor_sync(0xffffffffu, mx, off, 16));
            float mnew = fmaxf(mr[i], mx);
            float corr = __expf(mr[i] - mnew);
            float ls = 0.f;
#pragma unroll
            for (int j = 0; j < 4; j++) {
                s[i][j] = __expf(s[i][j] - mnew);
                ls += s[i][j];
            }
#pragma unroll
            for (int off = 8; off > 0; off >>= 1)
                ls += __shfl_xor_sync(0xffffffffu, ls, off, 16);
            lr[i] = lr[i] * corr + ls;
            mr[i] = mnew;
#pragma unroll
            for (int j = 0; j < 4; j++) acc[i][j] *= corr;
        }

        // stage P to shared for the PV GEMM
#pragma unroll
        for (int i = 0; i < 4; i++)
#pragma unroll
            for (int j = 0; j < 4; j++)
                Ps[(ty << 2) + i][(tx << 2) + j] = s[i][j];
        __syncthreads();

        // acc += P @ V
#pragma unroll 8
        for (int ss = 0; ss < 64; ss++) {
            float4 vv = *(const float4*)&Vs[ss][tx << 2];
            float vj[4] = {vv.x, vv.y, vv.z, vv.w};
            float p[4];
#pragma unroll
            for (int i = 0; i < 4; i++) p[i] = Ps[(ty << 2) + i][ss];
#pragma unroll
            for (int i = 0; i < 4; i++)
#pragma unroll
                for (int j = 0; j < 4; j++)
                    acc[i][j] = fmaf(p[i], vj[j], acc[i][j]);
        }
    }

    // write normalized output in [B, T, H*D] layout
#pragma unroll
    for (int i = 0; i < 4; i++) {
        int row = m0 + (ty << 2) + i;
        float inv = 1.f / lr[i];
        float4 o;
        o.x = acc[i][0] * inv; o.y = acc[i][1] * inv;
        o.z = acc[i][2] * inv; o.w = acc[i][3] * inv;
        *(float4*)(outa + ((size_t)(b * T_SEQ) + row) * DM + h * HD + (tx << 2)) = o;
    }
}

// ---------------------------------------------------------------------------
extern "C" void kernel_launch(void* const* d_in, const int* in_sizes, int n_in,
                              void* d_out, int out_size)
{
    const float* x      = (const float*)d_in[0];
    const float* w_qkv  = (const float*)d_in[1];
    const float* b_qkv  = (const float*)d_in[2];
    const float* w_proj = (const float*)d_in[3];
    const float* b_proj = (const float*)d_in[4];
    float* out = (float*)d_out;

    float* qkv_buf = nullptr;
    float* att_buf = nullptr;
    cudaGetSymbolAddress((void**)&qkv_buf, g_qkv);
    cudaGetSymbolAddress((void**)&att_buf, g_att);

    const int smem_attn = 4 * 64 * 68 * (int)sizeof(float);  // 69632 B
    cudaFuncSetAttribute(attn_kernel,
                         cudaFuncAttributeMaxDynamicSharedMemorySize, smem_attn);

    // 1) QKV projection: [4096,1024] @ [1024,3072] + b_qkv
    gemm_bias_kernel<<<dim3(24, 32), 256>>>(x, w_qkv, b_qkv, qkv_buf,
                                            4096, 3072, 1024);
    // 2) causal attention per (query-tile, b*h)
    attn_kernel<<<dim3(T_SEQ / 64, 2 * NH), 256, smem_attn>>>(qkv_buf, att_buf);
    // 3) output projection: [4096,1024] @ [1024,1024] + b_proj
    gemm_bias_kernel<<<dim3(8, 32), 256>>>(att_buf, w_proj, b_proj, out,
                                           4096, 1024, 1024);
}